// round 13
// baseline (speedup 1.0000x reference)
#include <cuda_runtime.h>

// SU2Attention: batch=1, seq=2048, heads=8, spinor_dim=2 (complex).
// Per head: Q=K are 4-dim real unit vectors u_j = s_j/||s_j||, logits u_i.u_j
// scaled by 1/sqrt(2) (bounded -> no max subtraction), softmax over keys,
// values are raw 4-vectors s_j.
//
// Output layout (verified R5-R12): PLANAR — real plane (2048*8*2 floats) then
// imag plane. d_in[0]=real, d_in[1]=imag.
//
// R13: 64 warps/SM. R8-R12 all ran 32 warps/SM (64-reg cap) and plateaued at
// issue ~50%. Here: QTILE=64, NQ=2, BLOCK=1024, grid=256 -> 2 co-resident
// blocks/SM (104 KB smem each, launch_bounds(1024,2) forces regs<=32) =
// 2048 threads/SM. LDS ratio 0.5 (L1 ~50%, under the R11 wall at 65%).

#define SEQ    2048
#define HEADS  8
#define QTILE  64
#define NQ     2
#define BLOCK  1024
#define NWARP  (BLOCK / 32)         // 32 key-splits
#define JCHUNK (SEQ / NWARP)        // 64 keys per warp

typedef unsigned long long u64_t;

__device__ __forceinline__ float2 fmul2(float2 a, float2 b) {
    float2 d;
    asm("mul.rn.f32x2 %0, %1, %2;"
        : "=l"(reinterpret_cast<u64_t&>(d))
        : "l"(reinterpret_cast<const u64_t&>(a)),
          "l"(reinterpret_cast<const u64_t&>(b)));
    return d;
}

__device__ __forceinline__ float2 ffma2(float2 a, float2 b, float2 c) {
    float2 d;
    asm("fma.rn.f32x2 %0, %1, %2, %3;"
        : "=l"(reinterpret_cast<u64_t&>(d))
        : "l"(reinterpret_cast<const u64_t&>(a)),
          "l"(reinterpret_cast<const u64_t&>(b)),
          "l"(reinterpret_cast<const u64_t&>(c)));
    return d;
}

__device__ __forceinline__ float ex2_approx(float x) {
    float r;
    asm("ex2.approx.ftz.f32 %0, %1;" : "=f"(r) : "f"(x));
    return r;
}

__global__ __launch_bounds__(BLOCK, 2)
void su2_attn_kernel(const float* __restrict__ p0,   // spinors_real
                     const float* __restrict__ p1,   // spinors_imag
                     float* __restrict__ out) {
    // Dynamic shared (104 KB):
    //   su:   SEQ float4 unit vectors       (32 KB)
    //   sv:   SEQ float4 raw vectors        (32 KB)
    //   pacc: NWARP x QTILE float4 partials (32 KB)
    //   pden: NWARP x QTILE float  partials ( 8 KB)
    extern __shared__ float4 smem[];
    float4* su   = smem;
    float4* sv   = smem + SEQ;
    float4* pacc = smem + 2 * SEQ;                       // [NWARP][QTILE]
    float*  pden = reinterpret_cast<float*>(pacc + NWARP * QTILE);

    const int h    = blockIdx.y;
    const int q0   = blockIdx.x * QTILE;
    const int lane = threadIdx.x & 31;
    const int warp = threadIdx.x >> 5;

    // Cooperative load + normalize of all SEQ vectors for this head.
    for (int j = threadIdx.x; j < SEQ; j += BLOCK) {
        const int base = (j * HEADS + h) * 2;
        float2 a = *reinterpret_cast<const float2*>(p0 + base);  // real (d0,d1)
        float2 b = *reinterpret_cast<const float2*>(p1 + base);  // imag (d0,d1)
        float x = a.x, y = a.y, z = b.x, w = b.y;
        float n2 = x*x + y*y + z*z + w*w;
        float rn = rsqrtf(n2);
        sv[j] = make_float4(x, y, z, w);
        su[j] = make_float4(x*rn, y*rn, z*rn, w*rn);
    }
    __syncthreads();

    // Each thread owns 2 queries: qA = q0+lane, qB = q0+lane+32.
    // Fold SCALE*log2(e) into the queries: exp(dot*SCALE) = 2^(dot').
    const float C = 0.70710678118654752f * 1.44269504088896341f;
    float2 qa01, qa23, qb01, qb23;
    {
        float4 qa = su[q0 + lane];
        float4 qb = su[q0 + lane + 32];
        qa01 = make_float2(qa.x * C, qa.y * C);
        qa23 = make_float2(qa.z * C, qa.w * C);
        qb01 = make_float2(qb.x * C, qb.y * C);
        qb23 = make_float2(qb.z * C, qb.w * C);
    }

    float2 aacc01 = make_float2(0.f, 0.f), aacc23 = make_float2(0.f, 0.f);
    float2 bacc01 = make_float2(0.f, 0.f), bacc23 = make_float2(0.f, 0.f);
    float adden = 0.f, bdden = 0.f;

    const int jlo = warp * JCHUNK;
    #pragma unroll 4
    for (int j = jlo; j < jlo + JCHUNK; ++j) {
        float4 u = su[j];                      // LDS.128, warp-broadcast
        float4 v = sv[j];                      // LDS.128, warp-broadcast
        float2 u01 = make_float2(u.x, u.y);
        float2 u23 = make_float2(u.z, u.w);
        float2 v01 = make_float2(v.x, v.y);
        float2 v23 = make_float2(v.z, v.w);

        float2 da = ffma2(qa23, u23, fmul2(qa01, u01));
        float2 db = ffma2(qb23, u23, fmul2(qb01, u01));
        float ea = ex2_approx(da.x + da.y);
        float eb = ex2_approx(db.x + db.y);

        float2 ea2 = make_float2(ea, ea);
        float2 eb2 = make_float2(eb, eb);
        aacc01 = ffma2(ea2, v01, aacc01);
        aacc23 = ffma2(ea2, v23, aacc23);
        bacc01 = ffma2(eb2, v01, bacc01);
        bacc23 = ffma2(eb2, v23, bacc23);
        adden += ea;
        bdden += eb;
    }

    pacc[warp * QTILE + lane] =
        make_float4(aacc01.x, aacc01.y, aacc23.x, aacc23.y);
    pden[warp * QTILE + lane] = adden;
    pacc[warp * QTILE + lane + 32] =
        make_float4(bacc01.x, bacc01.y, bacc23.x, bacc23.y);
    pden[warp * QTILE + lane + 32] = bdden;
    __syncthreads();

    // Stage A: 8 groups of 4 splits -> 8 partials per query (512 threads).
    if (threadIdx.x < 8 * QTILE) {
        const int q = threadIdx.x & (QTILE - 1);
        const int g = threadIdx.x >> 6;              // 0..7
        const int s0 = g * 4;
        float4 a = pacc[s0 * QTILE + q];
        float  d = pden[s0 * QTILE + q];
        #pragma unroll
        for (int s = 1; s < 4; ++s) {
            float4 b = pacc[(s0 + s) * QTILE + q];
            a.x += b.x; a.y += b.y; a.z += b.z; a.w += b.w;
            d += pden[(s0 + s) * QTILE + q];
        }
        pacc[s0 * QTILE + q] = a;
        pden[s0 * QTILE + q] = d;
    }
    __syncthreads();

    // Stage B: 64 threads finish the 8-way sum, normalize, store planar.
    if (threadIdx.x < QTILE) {
        const int q = threadIdx.x;
        float4 a = pacc[q];
        float  d = pden[q];
        #pragma unroll
        for (int g = 1; g < 8; ++g) {
            float4 b = pacc[g * 4 * QTILE + q];
            a.x += b.x; a.y += b.y; a.z += b.z; a.w += b.w;
            d += pden[g * 4 * QTILE + q];
        }
        const float inv = __frcp_rn(d);
        const int ohd = (q0 + q) * HEADS + h;
        // planar complex: real plane then imag plane, each (1,2048,8,2)
        *reinterpret_cast<float2*>(out + ohd * 2) =
            make_float2(a.x * inv, a.y * inv);
        *reinterpret_cast<float2*>(out + SEQ * HEADS * 2 + ohd * 2) =
            make_float2(a.z * inv, a.w * inv);
    }
}

extern "C" void kernel_launch(void* const* d_in, const int* in_sizes, int n_in,
                              void* d_out, int out_size) {
    const float* p0 = (const float*)d_in[0];
    const float* p1 = (const float*)d_in[1];
    float* out = (float*)d_out;

    const int shmem = 2 * SEQ * sizeof(float4)              // su + sv
                    + NWARP * QTILE * sizeof(float4)        // pacc
                    + NWARP * QTILE * sizeof(float);        // pden
    cudaFuncSetAttribute(su2_attn_kernel,
                         cudaFuncAttributeMaxDynamicSharedMemorySize, shmem);

    dim3 grid(SEQ / QTILE, HEADS);                          // 32 x 8 = 256
    dim3 block(BLOCK);
    su2_attn_kernel<<<grid, block, shmem>>>(p0, p1, out);
}

// round 14
// speedup vs baseline: 1.1969x; 1.1969x over previous
#include <cuda_runtime.h>
#include <cuda_fp16.h>

// SU2Attention: batch=1, seq=2048, heads=8, spinor_dim=2 (complex).
// Per head: Q=K are 4-dim real unit vectors u_j = s_j/||s_j||, logits u_i.u_j
// scaled by 1/sqrt(2) (bounded -> no max subtraction), softmax over keys,
// values are raw 4-vectors s_j.
//
// Output layout (verified R5-R13): PLANAR — real plane (2048*8*2 floats) then
// imag plane. d_in[0]=real, d_in[1]=imag.
//
// R14: fp16x2 mainloop. R8-R13 showed the fp32 path is stuck at the
// fma-service floor (FFMA2 rt=3 from register banking; scalar equivalent is
// identical). HFMA2 is rt=2 with 32-bit operands and 2 lanes/op, and
// ex2.approx.f16x2 gives 2 exps per MUFU slot: per key per 2 queries =
// 9 fma-pipe ops + 0.5 MUFU. Keys stored pre-duplicated (x,x)(y,y)(z,z)(w,w)
// as half2 so no lane-shuffle ops are needed. fp16 accumulators are flushed
// to fp32 every 16 keys to bound accumulation error (~3e-4).

#define SEQ    2048
#define HEADS  8
#define QTILE  128
#define BLOCK  1024
#define NWARP  (BLOCK / 32)         // 32 key-splits
#define JCHUNK (SEQ / NWARP)        // 64 keys per warp
#define FLUSH  16                   // fp16 -> fp32 flush interval

typedef unsigned long long u64_t;

__device__ __forceinline__ float2 fadd2(float2 a, float2 b) {
    float2 d;
    asm("add.rn.f32x2 %0, %1, %2;"
        : "=l"(reinterpret_cast<u64_t&>(d))
        : "l"(reinterpret_cast<const u64_t&>(a)),
          "l"(reinterpret_cast<const u64_t&>(b)));
    return d;
}

__device__ __forceinline__ half2 hexp2_2(half2 x) {
    half2 r;
    asm("ex2.approx.f16x2 %0, %1;"
        : "=r"(reinterpret_cast<unsigned&>(r))
        : "r"(reinterpret_cast<const unsigned&>(x)));
    return r;
}

__device__ __forceinline__ unsigned packdup(float a) {
    half2 h = __floats2half2_rn(a, a);
    return reinterpret_cast<unsigned&>(h);
}

__device__ __forceinline__ half2 u2h(unsigned a) {
    return reinterpret_cast<half2&>(a);
}

__global__ __launch_bounds__(BLOCK, 1)
void su2_attn_kernel(const float* __restrict__ p0,   // spinors_real
                     const float* __restrict__ p1,   // spinors_imag
                     float* __restrict__ out) {
    // Dynamic shared (144 KB):
    //   suh: SEQ uint4 — unit vecs, duplicated half2 (x,x)(y,y)(z,z)(w,w) (32 KB)
    //   svh: SEQ uint4 — raw  vecs, same layout                           (32 KB)
    //   pacc: NWARP x QTILE float4 partials                               (64 KB)
    //   pden: NWARP x QTILE float  partials                               (16 KB)
    extern __shared__ uint4 smem[];
    uint4*  suh  = smem;
    uint4*  svh  = smem + SEQ;
    float4* pacc = reinterpret_cast<float4*>(smem + 2 * SEQ);
    float*  pden = reinterpret_cast<float*>(pacc + NWARP * QTILE);

    const int h    = blockIdx.y;
    const int q0   = blockIdx.x * QTILE;
    const int lane = threadIdx.x & 31;
    const int warp = threadIdx.x >> 5;

    // Cooperative load + normalize + fp16-duplicate pack of all SEQ keys.
    for (int j = threadIdx.x; j < SEQ; j += BLOCK) {
        const int base = (j * HEADS + h) * 2;
        float2 a = *reinterpret_cast<const float2*>(p0 + base);  // real (d0,d1)
        float2 b = *reinterpret_cast<const float2*>(p1 + base);  // imag (d0,d1)
        float x = a.x, y = a.y, z = b.x, w = b.y;
        float n2 = x*x + y*y + z*z + w*w;
        float rn = rsqrtf(n2);
        uint4 vv;
        vv.x = packdup(x); vv.y = packdup(y); vv.z = packdup(z); vv.w = packdup(w);
        svh[j] = vv;
        uint4 uu;
        uu.x = packdup(x*rn); uu.y = packdup(y*rn);
        uu.z = packdup(z*rn); uu.w = packdup(w*rn);
        suh[j] = uu;
    }
    __syncthreads();

    // Each thread owns 4 queries as 2 pairs: pair p = (q0+lane+64p, +32).
    // Normalize in fp32, fold SCALE*log2(e), then pack pairs into half2.
    const float C = 0.70710678118654752f * 1.44269504088896341f;
    half2 qx[2], qy[2], qz[2], qw[2];
    #pragma unroll
    for (int p = 0; p < 2; ++p) {
        const int ia = q0 + lane + 64 * p;
        const int ib = ia + 32;
        float2 ar = *reinterpret_cast<const float2*>(p0 + (ia * HEADS + h) * 2);
        float2 ai = *reinterpret_cast<const float2*>(p1 + (ia * HEADS + h) * 2);
        float2 br = *reinterpret_cast<const float2*>(p0 + (ib * HEADS + h) * 2);
        float2 bi = *reinterpret_cast<const float2*>(p1 + (ib * HEADS + h) * 2);
        float rna = rsqrtf(ar.x*ar.x + ar.y*ar.y + ai.x*ai.x + ai.y*ai.y) * C;
        float rnb = rsqrtf(br.x*br.x + br.y*br.y + bi.x*bi.x + bi.y*bi.y) * C;
        qx[p] = __floats2half2_rn(ar.x * rna, br.x * rnb);
        qy[p] = __floats2half2_rn(ar.y * rna, br.y * rnb);
        qz[p] = __floats2half2_rn(ai.x * rna, bi.x * rnb);
        qw[p] = __floats2half2_rn(ai.y * rna, bi.y * rnb);
    }

    // fp16 short-range accumulators + fp32 long-range accumulators.
    const half2 hz2 = __floats2half2_rn(0.f, 0.f);
    half2 hx[2], hy[2], hzc[2], hw[2], hd[2];
    float2 fx[2], fy[2], fz[2], fw[2], fd[2];
    #pragma unroll
    for (int p = 0; p < 2; ++p) {
        hx[p] = hy[p] = hzc[p] = hw[p] = hd[p] = hz2;
        fx[p] = fy[p] = fz[p] = fw[p] = fd[p] = make_float2(0.f, 0.f);
    }

    const int jlo = warp * JCHUNK;
    for (int jc = 0; jc < JCHUNK; jc += FLUSH) {
        #pragma unroll
        for (int t = 0; t < FLUSH; ++t) {
            const int j = jlo + jc + t;
            uint4 uu = suh[j];                 // LDS.128: 4 duplicated half2
            uint4 vv = svh[j];
            half2 uxx = u2h(uu.x), uyy = u2h(uu.y);
            half2 uzz = u2h(uu.z), uww = u2h(uu.w);
            half2 vxx = u2h(vv.x), vyy = u2h(vv.y);
            half2 vzz = u2h(vv.z), vww = u2h(vv.w);
            #pragma unroll
            for (int p = 0; p < 2; ++p) {
                half2 t2 = __hfma2(qy[p], uyy, __hmul2(qx[p], uxx));
                t2 = __hfma2(qz[p], uzz, t2);
                t2 = __hfma2(qw[p], uww, t2);
                half2 e2 = hexp2_2(t2);        // 2 exps in one MUFU op
                hx[p]  = __hfma2(e2, vxx, hx[p]);
                hy[p]  = __hfma2(e2, vyy, hy[p]);
                hzc[p] = __hfma2(e2, vzz, hzc[p]);
                hw[p]  = __hfma2(e2, vww, hw[p]);
                hd[p]  = __hadd2(hd[p], e2);
            }
        }
        // Flush fp16 partials into fp32 accumulators.
        #pragma unroll
        for (int p = 0; p < 2; ++p) {
            fx[p] = fadd2(fx[p], __half22float2(hx[p]));
            fy[p] = fadd2(fy[p], __half22float2(hy[p]));
            fz[p] = fadd2(fz[p], __half22float2(hzc[p]));
            fw[p] = fadd2(fw[p], __half22float2(hw[p]));
            fd[p] = fadd2(fd[p], __half22float2(hd[p]));
            hx[p] = hy[p] = hzc[p] = hw[p] = hd[p] = hz2;
        }
    }

    // Write per-warp partials: pair p lo-half -> query lane+64p, hi -> +32.
    #pragma unroll
    for (int p = 0; p < 2; ++p) {
        const int qa = lane + 64 * p;
        pacc[warp * QTILE + qa] =
            make_float4(fx[p].x, fy[p].x, fz[p].x, fw[p].x);
        pden[warp * QTILE + qa] = fd[p].x;
        pacc[warp * QTILE + qa + 32] =
            make_float4(fx[p].y, fy[p].y, fz[p].y, fw[p].y);
        pden[warp * QTILE + qa + 32] = fd[p].y;
    }
    __syncthreads();

    // Stage A: 8 groups of 4 splits -> 8 partials per query.
    {
        const int q = threadIdx.x & (QTILE - 1);
        const int g = threadIdx.x >> 7;              // 0..7
        const int s0 = g * 4;
        float4 a = pacc[s0 * QTILE + q];
        float  d = pden[s0 * QTILE + q];
        #pragma unroll
        for (int s = 1; s < 4; ++s) {
            float4 b = pacc[(s0 + s) * QTILE + q];
            a.x += b.x; a.y += b.y; a.z += b.z; a.w += b.w;
            d += pden[(s0 + s) * QTILE + q];
        }
        __syncthreads();
        pacc[s0 * QTILE + q] = a;
        pden[s0 * QTILE + q] = d;
    }
    __syncthreads();

    // Stage B: 128 threads finish the 8-way sum, normalize, store planar.
    if (threadIdx.x < QTILE) {
        const int q = threadIdx.x;
        float4 a = pacc[q];
        float  d = pden[q];
        #pragma unroll
        for (int g = 1; g < 8; ++g) {
            float4 b = pacc[g * 4 * QTILE + q];
            a.x += b.x; a.y += b.y; a.z += b.z; a.w += b.w;
            d += pden[g * 4 * QTILE + q];
        }
        const float inv = __frcp_rn(d);
        const int ohd = (q0 + q) * HEADS + h;
        // planar complex: real plane then imag plane, each (1,2048,8,2)
        *reinterpret_cast<float2*>(out + ohd * 2) =
            make_float2(a.x * inv, a.y * inv);
        *reinterpret_cast<float2*>(out + SEQ * HEADS * 2 + ohd * 2) =
            make_float2(a.z * inv, a.w * inv);
    }
}

extern "C" void kernel_launch(void* const* d_in, const int* in_sizes, int n_in,
                              void* d_out, int out_size) {
    const float* p0 = (const float*)d_in[0];
    const float* p1 = (const float*)d_in[1];
    float* out = (float*)d_out;

    const int shmem = 2 * SEQ * sizeof(uint4)               // suh + svh
                    + NWARP * QTILE * sizeof(float4)        // pacc
                    + NWARP * QTILE * sizeof(float);        // pden
    cudaFuncSetAttribute(su2_attn_kernel,
                         cudaFuncAttributeMaxDynamicSharedMemorySize, shmem);

    dim3 grid(SEQ / QTILE, HEADS);
    dim3 block(BLOCK);
    su2_attn_kernel<<<grid, block, shmem>>>(p0, p1, out);
}

// round 15
// speedup vs baseline: 1.9263x; 1.6093x over previous
#include <cuda_runtime.h>
#include <cuda_fp16.h>

// SU2Attention: batch=1, seq=2048, heads=8, spinor_dim=2 (complex).
// Per head: Q=K are 4-dim real unit vectors u_j = s_j/||s_j||, logits u_i.u_j
// scaled by 1/sqrt(2) (bounded -> no max subtraction), softmax over keys,
// values are raw 4-vectors s_j.
//
// Output layout (verified R5-R14): PLANAR — real plane (2048*8*2 floats) then
// imag plane. d_in[0]=real, d_in[1]=imag.
//
// R15: tensor-core mainloop. R8-R14 established the fma pipe (at banking-
// degraded rt~3) as an inescapable ~10us scalar floor while tensor sat at 0%.
// S = Q.K^T via mma.m16n8k8 (dims padded 4->8), P = ex2(S) in f16 via
// cvt.f16x2 + ex2.approx.f16x2, O/den = P.[V|1] via mma.m16n8k16 with the
// FA2 fragment-reuse identity (S-mma C-frag == PV-mma A-frag layout).
// fp32 accumulation throughout (tensor-core C).

#define SEQ     2048
#define HEADS   8
#define QTILE   128
#define BLOCK   512
#define NWARP   16
#define VSTR    2056        // padded value-plane stride (halves): breaks bank aliasing

// ---- smem byte offsets (single dynamic buffer, 16B-aligned carve) ----
#define SK_OFF  0                       // skey : 2048 rows x 16B (8 halves: u*,0..)  32768
#define SQ_OFF  32768                   // squ  : 128 rows x 16B (C-folded queries)    2048
#define VP_OFF  34816                   // planes: 8 x VSTR halves                    32896
#define SA_OFF  67712                   // sacc : 2 x 8 x 16 x 8 f32                   8192
#define SM_TOT  75904

__device__ __forceinline__ unsigned cvt_f16x2(float hi, float lo) {
    unsigned d;
    asm("cvt.rn.f16x2.f32 %0, %1, %2;" : "=r"(d) : "f"(hi), "f"(lo));
    return d;
}

__device__ __forceinline__ unsigned hexp2_2(unsigned x) {
    unsigned r;
    asm("ex2.approx.f16x2 %0, %1;" : "=r"(r) : "r"(x));
    return r;
}

__device__ __forceinline__ void mma_s(float* c, unsigned a0, unsigned a1, unsigned b0) {
    float z = 0.f;
    asm("mma.sync.aligned.m16n8k8.row.col.f32.f16.f16.f32 "
        "{%0,%1,%2,%3}, {%4,%5}, {%6}, {%7,%8,%9,%10};"
        : "=f"(c[0]), "=f"(c[1]), "=f"(c[2]), "=f"(c[3])
        : "r"(a0), "r"(a1), "r"(b0), "f"(z), "f"(z), "f"(z), "f"(z));
}

__device__ __forceinline__ void mma_pv(float* c, unsigned p0, unsigned p1,
                                       unsigned p2, unsigned p3,
                                       unsigned b0, unsigned b1) {
    asm("mma.sync.aligned.m16n8k16.row.col.f32.f16.f16.f32 "
        "{%0,%1,%2,%3}, {%4,%5,%6,%7}, {%8,%9}, {%0,%1,%2,%3};"
        : "+f"(c[0]), "+f"(c[1]), "+f"(c[2]), "+f"(c[3])
        : "r"(p0), "r"(p1), "r"(p2), "r"(p3), "r"(b0), "r"(b1));
}

__global__ __launch_bounds__(BLOCK, 1)
void su2_attn_kernel(const float* __restrict__ p0,   // spinors_real
                     const float* __restrict__ p1,   // spinors_imag
                     float* __restrict__ out) {
    extern __shared__ char smem[];
    uint4*  skey   = reinterpret_cast<uint4*>(smem + SK_OFF);  // [2048] 8 halves/row
    uint4*  squ    = reinterpret_cast<uint4*>(smem + SQ_OFF);  // [128]  8 halves/row
    __half* planes = reinterpret_cast<__half*>(smem + VP_OFF); // [8][VSTR]
    float*  sacc   = reinterpret_cast<float*>(smem + SA_OFF);  // [2][8][16][8]

    const int h   = blockIdx.y;
    const int q0  = blockIdx.x * QTILE;
    const int tid = threadIdx.x;

    // SCALE * log2(e), folded into the queries so P = ex2(S).
    const float C = 0.70710678118654752f * 1.44269504088896341f;

    // ---- Preload: normalize keys, build mma-ready shared tiles ----
    for (int j = tid; j < SEQ; j += BLOCK) {
        const int base = (j * HEADS + h) * 2;
        float2 a = *reinterpret_cast<const float2*>(p0 + base);  // re (d0,d1)
        float2 b = *reinterpret_cast<const float2*>(p1 + base);  // im (d0,d1)
        float x = a.x, y = a.y, z = b.x, w = b.y;
        float rn = rsqrtf(x*x + y*y + z*z + w*w);
        // key row: unit vector in halves, dims 4..7 zero (k-dim pad)
        uint4 kr;
        kr.x = cvt_f16x2(y * rn, x * rn);   // {lo=ux, hi=uy}
        kr.y = cvt_f16x2(w * rn, z * rn);   // {lo=uz, hi=uw}
        kr.z = 0u;
        kr.w = 0u;
        skey[j] = kr;
        // value planes (component-major, consecutive keys): v0..v3, ones, 0,0,0
        planes[0 * VSTR + j] = __float2half(x);
        planes[1 * VSTR + j] = __float2half(y);
        planes[2 * VSTR + j] = __float2half(z);
        planes[3 * VSTR + j] = __float2half(w);
        planes[4 * VSTR + j] = __float2half(1.0f);   // denominator column
        planes[5 * VSTR + j] = __half(0.0f);
        planes[6 * VSTR + j] = __half(0.0f);
        planes[7 * VSTR + j] = __half(0.0f);
        // this block's query tile, with C folded
        if (j >= q0 && j < q0 + QTILE) {
            float rc = rn * C;
            uint4 qr;
            qr.x = cvt_f16x2(y * rc, x * rc);
            qr.y = cvt_f16x2(w * rc, z * rc);
            qr.z = 0u;
            qr.w = 0u;
            squ[j - q0] = qr;
        }
    }
    __syncthreads();

    // ---- Mainloop: warp = (q-subtile sq of 16 queries, key-half kh) ----
    const int lane = tid & 31;
    const int warp = tid >> 5;
    const int sq   = warp & 7;          // 0..7 -> queries sq*16..+15
    const int kh   = warp >> 3;         // 0..1 -> keys kh*1024..+1023
    const int lam  = lane & 3;          // lambda = lane % 4
    const int g    = lane >> 2;         // group  = lane / 4

    // A fragment (m16n8k8, row-major): a0 = Q[g][2l..2l+1], a1 = Q[g+8][...]
    const unsigned a0 = *reinterpret_cast<const unsigned*>(
        smem + SQ_OFF + (sq * 16 + g) * 16 + lam * 4);
    const unsigned a1 = *reinterpret_cast<const unsigned*>(
        smem + SQ_OFF + (sq * 16 + g + 8) * 16 + lam * 4);

    float acc[4] = {0.f, 0.f, 0.f, 0.f};

    for (int c = 0; c < 64; ++c) {
        const int kb = kh * 1024 + c * 16;
        // B frags for S-mma (col): b = K[2l..2l+1][key kb(+8)+g]
        unsigned b0 = *reinterpret_cast<const unsigned*>(
            smem + SK_OFF + (kb + g) * 16 + lam * 4);
        unsigned b1 = *reinterpret_cast<const unsigned*>(
            smem + SK_OFF + (kb + 8 + g) * 16 + lam * 4);
        float C0[4], C1[4];
        mma_s(C0, a0, a1, b0);              // S cols kb..kb+7
        mma_s(C1, a0, a1, b1);              // S cols kb+8..kb+15
        // P = ex2(S) packed as the PV-mma A fragment (FA2 identity):
        unsigned pp0 = hexp2_2(cvt_f16x2(C0[1], C0[0]));  // (g,   k 2l..2l+1)
        unsigned pp1 = hexp2_2(cvt_f16x2(C0[3], C0[2]));  // (g+8, k 2l..2l+1)
        unsigned pp2 = hexp2_2(cvt_f16x2(C1[1], C1[0]));  // (g,   k 2l+8..+9)
        unsigned pp3 = hexp2_2(cvt_f16x2(C1[3], C1[2]));  // (g+8, k 2l+8..+9)
        // B frags for PV-mma (col): V[k 2l..2l+1][comp g], V[k 2l+8..+9][g]
        unsigned vb0 = *reinterpret_cast<const unsigned*>(
            smem + VP_OFF + (g * VSTR + kb + 2 * lam) * 2);
        unsigned vb1 = *reinterpret_cast<const unsigned*>(
            smem + VP_OFF + (g * VSTR + kb + 8 + 2 * lam) * 2);
        mma_pv(acc, pp0, pp1, pp2, pp3, vb0, vb1);
    }

    // ---- Epilogue: stash C frags, combine key-halves, normalize, store ----
    {
        float* sa = sacc + ((kh * 8 + sq) * 16) * 8;
        sa[g * 8 + 2 * lam]           = acc[0];
        sa[g * 8 + 2 * lam + 1]       = acc[1];
        sa[(g + 8) * 8 + 2 * lam]     = acc[2];
        sa[(g + 8) * 8 + 2 * lam + 1] = acc[3];
    }
    __syncthreads();

    if (tid < QTILE) {
        const int q  = tid;
        const int ts = q >> 4;              // sub-tile
        const int r  = q & 15;              // row in sub-tile
        const float* A0 = sacc + ((0 * 8 + ts) * 16 + r) * 8;
        const float* A1 = sacc + ((1 * 8 + ts) * 16 + r) * 8;
        float vx = A0[0] + A1[0];
        float vy = A0[1] + A1[1];
        float vz = A0[2] + A1[2];
        float vw = A0[3] + A1[3];
        float dn = A0[4] + A1[4];
        const float inv = __frcp_rn(dn);
        const int ohd = (q0 + q) * HEADS + h;
        // planar complex: real plane then imag plane, each (1,2048,8,2)
        *reinterpret_cast<float2*>(out + ohd * 2) =
            make_float2(vx * inv, vy * inv);
        *reinterpret_cast<float2*>(out + SEQ * HEADS * 2 + ohd * 2) =
            make_float2(vz * inv, vw * inv);
    }
}

extern "C" void kernel_launch(void* const* d_in, const int* in_sizes, int n_in,
                              void* d_out, int out_size) {
    const float* p0 = (const float*)d_in[0];
    const float* p1 = (const float*)d_in[1];
    float* out = (float*)d_out;

    cudaFuncSetAttribute(su2_attn_kernel,
                         cudaFuncAttributeMaxDynamicSharedMemorySize, SM_TOT);

    dim3 grid(SEQ / QTILE, HEADS);      // 16 x 8 = 128 blocks
    dim3 block(BLOCK);
    su2_attn_kernel<<<grid, block, SM_TOT>>>(p0, p1, out);
}